// round 5
// baseline (speedup 1.0000x reference)
#include <cuda_runtime.h>
#include <cuda_fp16.h>
#include <math.h>

// Problem constants (fixed shapes per reference)
#define N_VN   8000
#define N_CN   4000
#define DV     3
#define DC     6
#define BATCH  1250
#define BP     1280          // padded batch stride
#define BP4    (BP/4)        // 320 threads = 4-wide lanes
#define NEDGE  (DV * N_VN)   // 24000
#define NUM_ITER 5
#define NTILE_V 250
#define NTILE_B 40

// Output layout: [c (B*n zeros)][c_hat (B*n)][llr (B*n)][loss (1)]
#define OUT_CHAT  ((size_t)BATCH * N_VN)
#define OUT_LLR   ((size_t)2 * BATCH * N_VN)
#define OUT_LOSS  ((size_t)3 * BATCH * N_VN)

struct alignas(8) h4 { __half2 a, b; };

// Scratch (device globals; no allocation allowed)
__device__ float    g_L[(size_t)N_VN * BP];          // 40 MB
__device__ float    g_xtot[(size_t)N_VN * BP];       // 40 MB
__device__ __half   g_msg_cn[(size_t)NEDGE * BP];    // 60 MB
__device__ int      g_cn_edges[NEDGE];
__device__ int      g_cn_cnt[N_CN];
__device__ double   g_loss;
__device__ unsigned g_bar_count;
__device__ volatile unsigned g_bar_gen;

__device__ __forceinline__ float tanh_approx(float x) {
    float r;
    asm("tanh.approx.f32 %0, %1;" : "=f"(r) : "f"(x));
    return r;
}

// Software grid barrier. All blocks guaranteed resident (grid = nSM * occ).
// Trailing __threadfence() is load-bearing: gpu-scope fence emits CCTL.IVALL,
// invalidating L1D lines cached from the previous phase (persistent kernels
// do not get the per-launch L1 flush).
__device__ __forceinline__ void grid_barrier() {
    __syncthreads();
    if (threadIdx.x == 0) {
        __threadfence();                         // publish this block's writes
        unsigned gen = g_bar_gen;
        if (atomicAdd(&g_bar_count, 1u) == gridDim.x - 1) {
            g_bar_count = 0u;
            __threadfence();
            g_bar_gen = gen + 1u;                // release
        } else {
            while (g_bar_gen == gen) { __nanosleep(64); }
        }
    }
    __syncthreads();
    __threadfence();                             // acquire + L1D invalidate
}

// ---------------------------------------------------------------------------
__global__ void zero_misc_kernel() {
    int i = blockIdx.x * blockDim.x + threadIdx.x;
    if (i < N_CN) g_cn_cnt[i] = 0;
    if (i == 0) { g_loss = 0.0; g_bar_count = 0u; g_bar_gen = 0u; }
}

// ---------------------------------------------------------------------------
// One persistent kernel: init -> CSR -> 5x(CN, VN) -> loss -> c_hat.
__global__ __launch_bounds__(BP4, 3) void bp_persistent(
    const float* __restrict__ noise, const float* __restrict__ weights,
    const int* __restrict__ cn_idx, const int* __restrict__ ebno_p,
    float* __restrict__ out)
{
    const int nb = gridDim.x;
    const int tx = threadIdx.x & 31;
    const int ty = threadIdx.x >> 5;             // 0..9
    __shared__ float tile[32][33];
    __shared__ float red[BP4 / 32];

    // sigma2 = 4/no, no = 1/(10^(ebno/10)*0.5)  =>  sigma2 = 2*10^(ebno/10)
    int iv = ebno_p[0];
    float eb = (iv >= -100 && iv <= 100) ? (float)iv : __int_as_float(iv);
    float sigma2 = 2.0f * exp10f(eb * 0.1f);
    float half_s2 = 0.5f * sigma2;
    float sq = sqrtf(sigma2);

    // ---- phase: init (llr out coalesced, transpose to L/x_tot; pad lanes 0) --
    for (int t = blockIdx.x; t < NTILE_V * NTILE_B; t += nb) {
        int tv = (t % NTILE_V) * 32;
        int tb = (t / NTILE_V) * 32;
        for (int r = ty; r < 32; r += 10) {
            int b = tb + r, v = tv + tx;
            float Lval = 0.0f;
            if (b < BATCH) {
                float llr = fmaf(sq, noise[(size_t)b * N_VN + v], -half_s2);
                out[OUT_LLR + (size_t)b * N_VN + v] = llr;
                Lval = -llr;
            }
            tile[r][tx] = Lval;
        }
        __syncthreads();
        for (int r = ty; r < 32; r += 10) {
            int v2 = tv + r, b2 = tb + tx;       // b2 < BP always
            float val = tile[tx][r];
            size_t base = (size_t)v2 * BP + b2;
            g_L[base] = val;
            g_xtot[base] = val;
        }
        __syncthreads();
    }
    // ---- phase: build CSR (counters pre-zeroed by zero_misc_kernel) ----
    for (int e = blockIdx.x * BP4 + threadIdx.x; e < NEDGE; e += nb * BP4) {
        int c = cn_idx[e];
        int s = atomicAdd(&g_cn_cnt[c], 1);
        g_cn_edges[c * DC + s] = e;              // order irrelevant (excl. product)
    }
    grid_barrier();

    float loss_acc = 0.0f;
    const size_t boff = (size_t)threadIdx.x * 4;
    const int b0 = threadIdx.x * 4;

    for (int it = 0; it < NUM_ITER; it++) {
        const bool first = (it == 0);

        // ---- CN phase ------------------------------------------------------
        for (int c = blockIdx.x; c < N_CN; c += nb) {
            int ed[DC]; int vr[DC]; float w2[DC];
#pragma unroll
            for (int j = 0; j < DC; j++) {       // uniform loads (warp-broadcast)
                ed[j] = g_cn_edges[c * DC + j];
                vr[j] = ed[j] % N_VN;            // vn_idx = tile(arange, DV)
                w2[j] = 0.5f * weights[ed[j]];
            }
            float4 x[DC];
#pragma unroll
            for (int j = 0; j < DC; j++)
                x[j] = *(const float4*)(g_xtot + (size_t)vr[j] * BP + boff);
            h4 mh[DC];
            if (!first) {
#pragma unroll
                for (int j = 0; j < DC; j++)
                    mh[j] = *(const h4*)(g_msg_cn + (size_t)ed[j] * BP + boff);
            }
            // t_j = tanh((x - mc) * w/2)  (tanh.approx saturates; clip-free
            // identical to clip(+-20)-then-tanh in fp32)
#pragma unroll
            for (int j = 0; j < DC; j++) {
                float4 mc = make_float4(0.f, 0.f, 0.f, 0.f);
                if (!first) {
                    float2 f0 = __half22float2(mh[j].a);
                    float2 f1 = __half22float2(mh[j].b);
                    mc = make_float4(f0.x, f0.y, f1.x, f1.y);
                }
#pragma unroll
                for (int k = 0; k < 4; k++)
                    (&x[j].x)[k] = tanh_approx(((&x[j].x)[k] - (&mc.x)[k]) * w2[j]);
            }
            // split-half exclusive signed product
            float A[4], B[4];
#pragma unroll
            for (int k = 0; k < 4; k++) {
                A[k] = (&x[0].x)[k] * (&x[1].x)[k] * (&x[2].x)[k];
                B[k] = (&x[3].x)[k] * (&x[4].x)[k] * (&x[5].x)[k];
            }
#pragma unroll
            for (int j = 0; j < DC; j++) {
                int ja = (j < 3) ? ((j + 1) % 3) : (3 + (j - 2) % 3);
                int jb = (j < 3) ? ((j + 2) % 3) : (3 + (j - 1) % 3);
                float4 msg;
#pragma unroll
                for (int k = 0; k < 4; k++) {
                    float other = (j < 3) ? B[k] : A[k];
                    float p = (&x[ja].x)[k] * (&x[jb].x)[k] * other;
                    p = fminf(fmaxf(p, -1.0f + 1e-7f), 1.0f - 1e-7f);
                    (&msg.x)[k] = __logf(__fdividef(1.0f + p, 1.0f - p)); // 2*atanh
                }
                h4 h;
                h.a = __floats2half2_rn(msg.x, msg.y);
                h.b = __floats2half2_rn(msg.z, msg.w);
                *(h4*)(g_msg_cn + (size_t)ed[j] * BP + boff) = h;
            }
        }
        grid_barrier();

        // ---- VN phase ------------------------------------------------------
        for (int v = blockIdx.x; v < N_VN; v += nb) {
            size_t base = (size_t)v * BP + boff;
            h4 h0 = *(const h4*)(g_msg_cn + base);
            h4 h1 = *(const h4*)(g_msg_cn + (size_t)N_VN * BP + base);
            h4 h2 = *(const h4*)(g_msg_cn + (size_t)2 * N_VN * BP + base);
            const float4 Lv = *(const float4*)(g_L + base);

            float2 s0 = __half22float2(__hadd2(__hadd2(h0.a, h1.a), h2.a));
            float2 s1 = __half22float2(__hadd2(__hadd2(h0.b, h1.b), h2.b));

            float4 x;
            x.x = Lv.x + s0.x;  x.y = Lv.y + s0.y;
            x.z = Lv.z + s1.x;  x.w = Lv.w + s1.y;
            *(float4*)(g_xtot + base) = x;

#pragma unroll
            for (int k = 0; k < 4; k++) {
                if (b0 + k < BATCH) {
                    float ch = -(&x.x)[k];
                    loss_acc += fmaxf(ch, 0.0f)
                              + __logf(1.0f + __expf(-fabsf(ch)));
                }
            }
        }
        grid_barrier();
    }

    // ---- loss: one reduction + one atomic per block ----
    for (int o = 16; o > 0; o >>= 1)
        loss_acc += __shfl_down_sync(0xffffffffu, loss_acc, o);
    if (tx == 0) red[ty] = loss_acc;
    __syncthreads();
    if (threadIdx.x == 0) {
        float s = 0.0f;
#pragma unroll
        for (int w = 0; w < BP4 / 32; w++) s += red[w];
        atomicAdd(&g_loss, (double)s);
    }
    grid_barrier();
    if (blockIdx.x == 0 && threadIdx.x == 0) {
        double denom = (double)NUM_ITER * (double)BATCH * (double)N_VN;
        out[OUT_LOSS] = (float)(g_loss / denom);
    }

    // ---- phase: c_hat = -x_tot.T (tiled transpose, coalesced writes) ----
    for (int t = blockIdx.x; t < NTILE_V * NTILE_B; t += nb) {
        int tv = (t % NTILE_V) * 32;
        int tb = (t / NTILE_V) * 32;
        __syncthreads();
        for (int r = ty; r < 32; r += 10)
            tile[r][tx] = g_xtot[(size_t)(tv + r) * BP + tb + tx];
        __syncthreads();
        for (int r = ty; r < 32; r += 10) {
            int b = tb + r;
            if (b < BATCH)
                out[OUT_CHAT + (size_t)b * N_VN + tv + tx] = -tile[tx][r];
        }
    }
}

// ---------------------------------------------------------------------------
extern "C" void kernel_launch(void* const* d_in, const int* in_sizes, int n_in,
                              void* d_out, int out_size) {
    const float* noise   = (const float*)d_in[0];
    const float* weights = (const float*)d_in[1];
    // d_in[2] = vn_idx (tile(arange(N_VN), DV) by construction; implicit)
    const int*   cn_idx  = (const int*)d_in[3];
    const int*   ebno    = (const int*)d_in[4];
    float* out = (float*)d_out;

    // c output = zeros
    cudaMemsetAsync(out, 0, (size_t)BATCH * N_VN * sizeof(float));

    zero_misc_kernel<<<(N_CN + 255) / 256, 256>>>();

    // Grid sized for guaranteed co-residency (spin barrier must not deadlock)
    int dev = 0;
    cudaGetDevice(&dev);
    int nsm = 148;
    cudaDeviceGetAttribute(&nsm, cudaDevAttrMultiProcessorCount, dev);
    int occ = 1;
    cudaOccupancyMaxActiveBlocksPerMultiprocessor(&occ, bp_persistent, BP4, 0);
    if (occ > 3) occ = 3;
    if (occ < 1) occ = 1;

    bp_persistent<<<nsm * occ, BP4>>>(noise, weights, cn_idx, ebno, out);
}

// round 6
// speedup vs baseline: 1.2265x; 1.2265x over previous
#include <cuda_runtime.h>
#include <cuda_fp16.h>
#include <math.h>

// Problem constants (fixed shapes per reference)
#define N_VN   8000
#define N_CN   4000
#define DV     3
#define DC     6
#define BATCH  1250
#define BP     1280          // padded batch stride (128B aligned rows)
#define BP4    (BP/4)        // 320 4-wide lanes
#define NEDGE  (DV * N_VN)   // 24000
#define NUM_ITER 5

// Output layout: [c (B*n zeros)][c_hat (B*n)][llr (B*n)][loss (1)]
#define OUT_CHAT  ((size_t)BATCH * N_VN)
#define OUT_LLR   ((size_t)2 * BATCH * N_VN)
#define OUT_LOSS  ((size_t)3 * BATCH * N_VN)

struct alignas(8) h4 { __half2 a, b; };

// Scratch (device globals; no allocation allowed)
__device__ float  g_L[(size_t)N_VN * BP];          // 40 MB  L[v][b]
__device__ float  g_xtot[(size_t)N_VN * BP];       // 40 MB  x_tot[v][b]
__device__ __half g_msg_cn[(size_t)NEDGE * BP];    // 60 MB  msg_cn[e][b] fp16
__device__ int    g_cn_edges[NEDGE];               // CSR: 6 edges per CN
__device__ int    g_cn_cnt[N_CN];
__device__ double g_loss;

__device__ __forceinline__ float tanh_approx(float x) {
    float r;
    asm("tanh.approx.f32 %0, %1;" : "=f"(r) : "f"(x));
    return r;
}

// ---------------------------------------------------------------------------
// Init: llr output (coalesced), transpose to L[v][b], x_tot = L. Also zeroes
// CSR counters + loss (so zero_misc launch is gone). Pad lanes get zeros.
__global__ void init_kernel(const float* __restrict__ noise,
                            const int* __restrict__ ebno_p,
                            float* __restrict__ out) {
    cudaGridDependencySynchronize();
    __shared__ float tile[32][33];

    // misc zeroing, spread across the grid
    int gid = (blockIdx.y * gridDim.x + blockIdx.x) * 1024
            + threadIdx.y * 32 + threadIdx.x;
    if (gid < N_CN) g_cn_cnt[gid] = 0;
    if (gid == N_CN) g_loss = 0.0;

    // sigma2 = 4/no, no = 1/(10^(ebno/10)*0.5)  =>  sigma2 = 2*10^(ebno/10)
    int iv = ebno_p[0];
    float eb = (iv >= -100 && iv <= 100) ? (float)iv : __int_as_float(iv);
    float sigma2 = 2.0f * exp10f(eb * 0.1f);
    float half_s2 = 0.5f * sigma2;
    float sq = sqrtf(sigma2);

    int v = blockIdx.x * 32 + threadIdx.x;   // 250 tiles * 32 == 8000 exact
    int b = blockIdx.y * 32 + threadIdx.y;

    float Lval = 0.0f;
    if (b < BATCH) {
        float llr = fmaf(sq, noise[(size_t)b * N_VN + v], -half_s2);
        out[OUT_LLR + (size_t)b * N_VN + v] = llr;   // coalesced
        Lval = -llr;                                 // L = -llr.T
    }
    tile[threadIdx.y][threadIdx.x] = Lval;
    __syncthreads();

    int v2 = blockIdx.x * 32 + threadIdx.y;
    int b2 = blockIdx.y * 32 + threadIdx.x;          // always < BP
    float val = tile[threadIdx.x][threadIdx.y];      // 0 in padding
    size_t base = (size_t)v2 * BP + b2;
    g_L[base] = val;
    g_xtot[base] = val;
    cudaTriggerProgrammaticLaunchCompletion();
}

// ---------------------------------------------------------------------------
__global__ void build_csr_kernel(const int* __restrict__ cn_idx) {
    cudaGridDependencySynchronize();   // counters zeroed by init
    int e = blockIdx.x * blockDim.x + threadIdx.x;
    if (e < NEDGE) {
        int c = cn_idx[e];
        int s = atomicAdd(&g_cn_cnt[c], 1);
        g_cn_edges[c * DC + s] = e;    // order irrelevant (exclusive product)
    }
    cudaTriggerProgrammaticLaunchCompletion();
}

// ---------------------------------------------------------------------------
// CN update, 4 batch lanes / thread (R4-proven).
__global__ __launch_bounds__(BP4, 4) void cn_kernel(const float* __restrict__ weights,
                                                    int first) {
    cudaGridDependencySynchronize();
    __shared__ int   sv[DC];
    __shared__ int   se[DC];
    __shared__ float sw2[DC];
    int c = blockIdx.x;
    if (threadIdx.x < DC) {
        int e = g_cn_edges[c * DC + threadIdx.x];
        se[threadIdx.x] = e;
        sv[threadIdx.x] = e % N_VN;    // vn_idx = tile(arange(N_VN), DV)
        sw2[threadIdx.x] = 0.5f * weights[e];
    }
    __syncthreads();

    size_t boff = (size_t)threadIdx.x * 4;

    float4 x[DC];
#pragma unroll
    for (int j = 0; j < DC; j++)
        x[j] = *(const float4*)(g_xtot + (size_t)sv[j] * BP + boff);

    h4 mh[DC];
    if (!first) {
#pragma unroll
        for (int j = 0; j < DC; j++)
            mh[j] = *(const h4*)(g_msg_cn + (size_t)se[j] * BP + boff);
    }

    // t_j = tanh((x - mc) * w/2); tanh.approx saturates, equal to
    // reference's clip(+-20)-then-tanh in fp32.
#pragma unroll
    for (int j = 0; j < DC; j++) {
        float w2 = sw2[j];
        float4 mc = make_float4(0.f, 0.f, 0.f, 0.f);
        if (!first) {
            float2 f0 = __half22float2(mh[j].a);
            float2 f1 = __half22float2(mh[j].b);
            mc = make_float4(f0.x, f0.y, f1.x, f1.y);
        }
#pragma unroll
        for (int k = 0; k < 4; k++)
            (&x[j].x)[k] = tanh_approx(((&x[j].x)[k] - (&mc.x)[k]) * w2);
    }

    // split-half exclusive signed product
    float A[4], B[4];
#pragma unroll
    for (int k = 0; k < 4; k++) {
        A[k] = (&x[0].x)[k] * (&x[1].x)[k] * (&x[2].x)[k];
        B[k] = (&x[3].x)[k] * (&x[4].x)[k] * (&x[5].x)[k];
    }
#pragma unroll
    for (int j = 0; j < DC; j++) {
        int ja = (j < 3) ? ((j + 1) % 3) : (3 + (j - 2) % 3);
        int jb = (j < 3) ? ((j + 2) % 3) : (3 + (j - 1) % 3);
        float4 msg;
#pragma unroll
        for (int k = 0; k < 4; k++) {
            float other = (j < 3) ? B[k] : A[k];
            float p = (&x[ja].x)[k] * (&x[jb].x)[k] * other;
            p = fminf(fmaxf(p, -1.0f + 1e-7f), 1.0f - 1e-7f);
            (&msg.x)[k] = __logf(__fdividef(1.0f + p, 1.0f - p));  // 2*atanh
        }
        h4 h;
        h.a = __floats2half2_rn(msg.x, msg.y);
        h.b = __floats2half2_rn(msg.z, msg.w);
        *(h4*)(g_msg_cn + (size_t)se[j] * BP + boff) = h;
    }
    cudaTriggerProgrammaticLaunchCompletion();
}

// ---------------------------------------------------------------------------
// VN update (iterations 0..NUM_ITER-2): x_tot = L + sum(msg); accumulate loss.
// 2 VNs per 640-thread block (R4-proven).
__global__ __launch_bounds__(2 * BP4) void vn_kernel() {
    cudaGridDependencySynchronize();
    int v = blockIdx.x * 2 + (threadIdx.x / BP4);
    int lane = threadIdx.x % BP4;
    size_t base = (size_t)v * BP + (size_t)lane * 4;

    h4 h0 = *(const h4*)(g_msg_cn + base);
    h4 h1 = *(const h4*)(g_msg_cn + (size_t)N_VN * BP + base);
    h4 h2 = *(const h4*)(g_msg_cn + (size_t)2 * N_VN * BP + base);
    const float4 Lv = *(const float4*)(g_L + base);

    float2 s0 = __half22float2(__hadd2(__hadd2(h0.a, h1.a), h2.a));
    float2 s1 = __half22float2(__hadd2(__hadd2(h0.b, h1.b), h2.b));

    float4 x;
    x.x = Lv.x + s0.x;  x.y = Lv.y + s0.y;
    x.z = Lv.z + s1.x;  x.w = Lv.w + s1.y;
    *(float4*)(g_xtot + base) = x;
    cudaTriggerProgrammaticLaunchCompletion();

    float sp = 0.0f;
    int b0 = lane * 4;
#pragma unroll
    for (int k = 0; k < 4; k++) {
        if (b0 + k < BATCH) {
            float ch = -(&x.x)[k];
            sp += fmaxf(ch, 0.0f) + __logf(1.0f + __expf(-fabsf(ch)));
        }
    }
    for (int o = 16; o > 0; o >>= 1)
        sp += __shfl_down_sync(0xffffffffu, sp, o);
    __shared__ float red[(2 * BP4) / 32];
    if ((threadIdx.x & 31) == 0) red[threadIdx.x >> 5] = sp;
    __syncthreads();
    if (threadIdx.x == 0) {
        float s = 0.0f;
#pragma unroll
        for (int w = 0; w < (2 * BP4) / 32; w++) s += red[w];
        atomicAdd(&g_loss, (double)s);
    }
}

// ---------------------------------------------------------------------------
// Last VN iteration fused with c_hat transpose: processes a 32-VN tile,
// computes x_tot in registers, loss, and writes c_hat[b][v] coalesced via
// a shared transpose tile. x_tot is NOT written back (nothing consumes it).
__global__ __launch_bounds__(BP4) void vn_last_kernel(float* __restrict__ out) {
    cudaGridDependencySynchronize();
    __shared__ float tile[32][129];   // [v_local][b_local], pad for write phase
    __shared__ float red[BP4 / 32];

    const int v0 = blockIdx.x * 32;
    const int tx = threadIdx.x & 31;
    const int ty = threadIdx.x >> 5;   // warp 0..9
    float sp = 0.0f;

    for (int bc = 0; bc < BP / 128; bc++) {          // 10 chunks of 128 b
        // compute phase: rows r = ty, ty+10, ty+20, (+30 for ty<2)
#pragma unroll
        for (int r = ty; r < 32; r += 10) {
            int v = v0 + r;
            int b = bc * 128 + tx * 4;
            size_t base = (size_t)v * BP + b;
            h4 h0 = *(const h4*)(g_msg_cn + base);
            h4 h1 = *(const h4*)(g_msg_cn + (size_t)N_VN * BP + base);
            h4 h2 = *(const h4*)(g_msg_cn + (size_t)2 * N_VN * BP + base);
            const float4 Lv = *(const float4*)(g_L + base);
            float2 s0 = __half22float2(__hadd2(__hadd2(h0.a, h1.a), h2.a));
            float2 s1 = __half22float2(__hadd2(__hadd2(h0.b, h1.b), h2.b));
            float xv[4];
            xv[0] = Lv.x + s0.x;  xv[1] = Lv.y + s0.y;
            xv[2] = Lv.z + s1.x;  xv[3] = Lv.w + s1.y;
#pragma unroll
            for (int k = 0; k < 4; k++) {
                tile[r][tx * 4 + k] = xv[k];
                if (b + k < BATCH) {
                    float ch = -xv[k];
                    sp += fmaxf(ch, 0.0f) + __logf(1.0f + __expf(-fabsf(ch)));
                }
            }
        }
        __syncthreads();
        // write phase: out[b][v0+tx] = -tile[tx][b_local], coalesced over tx
        for (int m = ty; m < 128; m += 10) {
            int b = bc * 128 + m;
            if (b < BATCH)
                out[OUT_CHAT + (size_t)b * N_VN + v0 + tx] = -tile[tx][m];
        }
        __syncthreads();
    }

    for (int o = 16; o > 0; o >>= 1)
        sp += __shfl_down_sync(0xffffffffu, sp, o);
    if (tx == 0) red[ty] = sp;
    __syncthreads();
    if (threadIdx.x == 0) {
        float s = 0.0f;
#pragma unroll
        for (int w = 0; w < BP4 / 32; w++) s += red[w];
        atomicAdd(&g_loss, (double)s);
    }
}

// ---------------------------------------------------------------------------
__global__ void loss_kernel(float* __restrict__ out) {
    cudaGridDependencySynchronize();
    if (threadIdx.x == 0 && blockIdx.x == 0) {
        double denom = (double)NUM_ITER * (double)BATCH * (double)N_VN;
        out[OUT_LOSS] = (float)(g_loss / denom);
    }
}

// ---------------------------------------------------------------------------
// PDL launch helper: overlap next-kernel dispatch with current-kernel tail.
template <typename... Args>
static void launch_pdl(void (*kern)(Args...), dim3 grid, dim3 block,
                       Args... args) {
    cudaLaunchConfig_t cfg = {};
    cfg.gridDim = grid;
    cfg.blockDim = block;
    cudaLaunchAttribute attr[1];
    attr[0].id = cudaLaunchAttributeProgrammaticStreamSerialization;
    attr[0].val.programmaticStreamSerializationAllowed = 1;
    cfg.attrs = attr;
    cfg.numAttrs = 1;
    cudaLaunchKernelEx(&cfg, kern, args...);
}

extern "C" void kernel_launch(void* const* d_in, const int* in_sizes, int n_in,
                              void* d_out, int out_size) {
    const float* noise   = (const float*)d_in[0];
    const float* weights = (const float*)d_in[1];
    // d_in[2] = vn_idx (tile(arange(N_VN), DV) by construction; implicit)
    const int*   cn_idx  = (const int*)d_in[3];
    const int*   ebno    = (const int*)d_in[4];
    float* out = (float*)d_out;

    // c output = zeros
    cudaMemsetAsync(out, 0, (size_t)BATCH * N_VN * sizeof(float));

    dim3 tb(32, 32);
    dim3 tg(N_VN / 32, (BATCH + 31) / 32);   // 250 x 40
    launch_pdl(init_kernel, tg, tb, noise, ebno, out);
    launch_pdl(build_csr_kernel, dim3((NEDGE + 255) / 256), dim3(256), cn_idx);

    for (int it = 0; it < NUM_ITER; it++) {
        launch_pdl(cn_kernel, dim3(N_CN), dim3(BP4), weights, it == 0 ? 1 : 0);
        if (it < NUM_ITER - 1)
            launch_pdl(vn_kernel, dim3(N_VN / 2), dim3(2 * BP4));
        else
            launch_pdl(vn_last_kernel, dim3(N_VN / 32), dim3(BP4), out);
    }
    launch_pdl(loss_kernel, dim3(1), dim3(32), out);
}

// round 8
// speedup vs baseline: 1.2411x; 1.0119x over previous
#include <cuda_runtime.h>
#include <cuda_fp16.h>
#include <math.h>

// Problem constants (fixed shapes per reference)
#define N_VN   8000
#define N_CN   4000
#define DV     3
#define DC     6
#define BATCH  1250
#define BP     1280          // padded batch stride (128B aligned rows)
#define BP4    (BP/4)        // 320 4-wide lanes
#define NEDGE  (DV * N_VN)   // 24000
#define NUM_ITER 5

// Output layout: [c (B*n zeros)][c_hat (B*n)][llr (B*n)][loss (1)]
#define OUT_CHAT  ((size_t)BATCH * N_VN)
#define OUT_LLR   ((size_t)2 * BATCH * N_VN)
#define OUT_LOSS  ((size_t)3 * BATCH * N_VN)

struct alignas(8) h4 { __half2 a, b; };

// Scratch (device globals; no allocation allowed)
__device__ float  g_L[(size_t)N_VN * BP];          // 40 MB  L[v][b]
__device__ __half g_msgA[(size_t)NEDGE * BP];      // 60 MB  message ping buffer
__device__ __half g_msgB[(size_t)NEDGE * BP];      // 60 MB  message pong buffer
__device__ int    g_cn_edges[NEDGE];               // CSR: 6 edges per CN
__device__ int    g_cn_cnt[N_CN];
__device__ double g_loss;

__device__ __forceinline__ float tanh_approx(float x) {
    float r;
    asm("tanh.approx.f32 %0, %1;" : "=f"(r) : "f"(x));
    return r;
}

// ---------------------------------------------------------------------------
// Init: llr output (coalesced), transpose to L[v][b]. Zeroes CSR counters +
// loss. Pad batch lanes [1250,1280) get zeros.
__global__ void init_kernel(const float* __restrict__ noise,
                            const int* __restrict__ ebno_p,
                            float* __restrict__ out) {
    cudaGridDependencySynchronize();
    __shared__ float tile[32][33];

    int gid = (blockIdx.y * gridDim.x + blockIdx.x) * 1024
            + threadIdx.y * 32 + threadIdx.x;
    if (gid < N_CN) g_cn_cnt[gid] = 0;
    if (gid == N_CN) g_loss = 0.0;

    // sigma2 = 4/no, no = 1/(10^(ebno/10)*0.5)  =>  sigma2 = 2*10^(ebno/10)
    int iv = ebno_p[0];
    float eb = (iv >= -100 && iv <= 100) ? (float)iv : __int_as_float(iv);
    float sigma2 = 2.0f * exp10f(eb * 0.1f);
    float half_s2 = 0.5f * sigma2;
    float sq = sqrtf(sigma2);

    int v = blockIdx.x * 32 + threadIdx.x;   // 250 tiles * 32 == 8000 exact
    int b = blockIdx.y * 32 + threadIdx.y;

    float Lval = 0.0f;
    if (b < BATCH) {
        float llr = fmaf(sq, noise[(size_t)b * N_VN + v], -half_s2);
        out[OUT_LLR + (size_t)b * N_VN + v] = llr;   // coalesced
        Lval = -llr;                                 // L = -llr.T
    }
    tile[threadIdx.y][threadIdx.x] = Lval;
    __syncthreads();

    int v2 = blockIdx.x * 32 + threadIdx.y;
    int b2 = blockIdx.y * 32 + threadIdx.x;          // always < BP
    g_L[(size_t)v2 * BP + b2] = tile[threadIdx.x][threadIdx.y];
    cudaTriggerProgrammaticLaunchCompletion();
}

// ---------------------------------------------------------------------------
__global__ void build_csr_kernel(const int* __restrict__ cn_idx) {
    cudaGridDependencySynchronize();   // counters zeroed by init
    int e = blockIdx.x * blockDim.x + threadIdx.x;
    if (e < NEDGE) {
        int c = cn_idx[e];
        int s = atomicAdd(&g_cn_cnt[c], 1);
        g_cn_edges[c * DC + s] = e;    // order irrelevant (exclusive product)
    }
    cudaTriggerProgrammaticLaunchCompletion();
}

// ---------------------------------------------------------------------------
// Fused CN update (VN recompute folded in), 4 batch lanes / thread.
// DOUBLE-BUFFERED: reads previous-iteration messages from rbuf, writes new
// messages to wbuf (rbuf != wbuf) -- no same-launch RAW race across CNs.
// For each of the CN's 6 edges e=(v,layer l):
//   x_v = L[v] + (rbuf[v] + rbuf[v+N] + rbuf[v+2N])   (half2 adds)
//   t_j = tanh((x_v - rbuf[e]) * w/2)                 (it=0: msgs are 0)
//   layer-0 edges with it>=1: loss += softplus(-x_v)   -> loss of iter it-1
// Then exclusive signed product over the 6 edges, msg = 2*atanh, fp16 store.
__global__ __launch_bounds__(BP4, 4) void fused_cn_kernel(
        const float* __restrict__ weights, int it) {
    cudaGridDependencySynchronize();
    const __half* __restrict__ rbuf = (it & 1) ? g_msgA : g_msgB;  // prev iter
    __half* __restrict__       wbuf = (it & 1) ? g_msgB : g_msgA;  // this iter

    __shared__ int   se[DC];
    __shared__ int   sv[DC];
    __shared__ int   sl[DC];
    __shared__ float sw2[DC];
    __shared__ float red[BP4 / 32];

    int c = blockIdx.x;
    if (threadIdx.x < DC) {
        int e = g_cn_edges[c * DC + threadIdx.x];
        se[threadIdx.x] = e;
        sv[threadIdx.x] = e % N_VN;    // vn_idx = tile(arange(N_VN), DV)
        sl[threadIdx.x] = e / N_VN;    // layer 0..2
        sw2[threadIdx.x] = 0.5f * weights[e];
    }
    __syncthreads();

    const bool first = (it == 0);
    const size_t boff = (size_t)threadIdx.x * 4;
    const int b0 = threadIdx.x * 4;
    float loss_acc = 0.0f;

    float4 t[DC];
#pragma unroll
    for (int j = 0; j < DC; j++) {
        const int v = sv[j];
        float4 x = *(const float4*)(g_L + (size_t)v * BP + boff);
        float4 marg = make_float4(0.f, 0.f, 0.f, 0.f);
        if (!first) {
            h4 m0 = *(const h4*)(rbuf + (size_t)v * BP + boff);
            h4 m1 = *(const h4*)(rbuf + (size_t)(v + N_VN) * BP + boff);
            h4 m2 = *(const h4*)(rbuf + (size_t)(v + 2 * N_VN) * BP + boff);
            // x = L + half2-sum (bit-identical to the old vn_kernel path)
            float2 s0 = __half22float2(__hadd2(__hadd2(m0.a, m1.a), m2.a));
            float2 s1 = __half22float2(__hadd2(__hadd2(m0.b, m1.b), m2.b));
            x.x += s0.x;  x.y += s0.y;  x.z += s1.x;  x.w += s1.y;
            // select this edge's own message (by layer)
            int l = sl[j];
            __half2 ma = (l == 0) ? m0.a : (l == 1) ? m1.a : m2.a;
            __half2 mb = (l == 0) ? m0.b : (l == 1) ? m1.b : m2.b;
            float2 f0 = __half22float2(ma);
            float2 f1 = __half22float2(mb);
            marg = make_float4(f0.x, f0.y, f1.x, f1.y);
            // loss of iteration it-1, owned by the VN's unique layer-0 edge
            if (l == 0) {
#pragma unroll
                for (int k = 0; k < 4; k++) {
                    if (b0 + k < BATCH) {
                        float ch = -(&x.x)[k];
                        loss_acc += fmaxf(ch, 0.0f)
                                  + __logf(1.0f + __expf(-fabsf(ch)));
                    }
                }
            }
        }
        float w2 = sw2[j];
#pragma unroll
        for (int k = 0; k < 4; k++)
            (&t[j].x)[k] = tanh_approx(((&x.x)[k] - (&marg.x)[k]) * w2);
    }

    // split-half exclusive signed product
    float A[4], B[4];
#pragma unroll
    for (int k = 0; k < 4; k++) {
        A[k] = (&t[0].x)[k] * (&t[1].x)[k] * (&t[2].x)[k];
        B[k] = (&t[3].x)[k] * (&t[4].x)[k] * (&t[5].x)[k];
    }
#pragma unroll
    for (int j = 0; j < DC; j++) {
        int ja = (j < 3) ? ((j + 1) % 3) : (3 + (j - 2) % 3);
        int jb = (j < 3) ? ((j + 2) % 3) : (3 + (j - 1) % 3);
        float4 msg;
#pragma unroll
        for (int k = 0; k < 4; k++) {
            float other = (j < 3) ? B[k] : A[k];
            float p = (&t[ja].x)[k] * (&t[jb].x)[k] * other;
            p = fminf(fmaxf(p, -1.0f + 1e-7f), 1.0f - 1e-7f);
            (&msg.x)[k] = __logf(__fdividef(1.0f + p, 1.0f - p));  // 2*atanh
        }
        h4 h;
        h.a = __floats2half2_rn(msg.x, msg.y);
        h.b = __floats2half2_rn(msg.z, msg.w);
        *(h4*)(wbuf + (size_t)se[j] * BP + boff) = h;
    }
    cudaTriggerProgrammaticLaunchCompletion();

    if (!first) {
        for (int o = 16; o > 0; o >>= 1)
            loss_acc += __shfl_down_sync(0xffffffffu, loss_acc, o);
        if ((threadIdx.x & 31) == 0) red[threadIdx.x >> 5] = loss_acc;
        __syncthreads();
        if (threadIdx.x == 0) {
            float s = 0.0f;
#pragma unroll
            for (int w = 0; w < BP4 / 32; w++) s += red[w];
            atomicAdd(&g_loss, (double)s);
        }
    }
}

// ---------------------------------------------------------------------------
// Final VN pass fused with c_hat transpose: x_4 per 32-VN tile, its loss,
// and c_hat[b][v] = -x written coalesced via shared transpose.
// Reads the buffer written by iteration NUM_ITER-1 (= g_msgA for it=4 even).
__global__ __launch_bounds__(BP4) void vn_last_kernel(float* __restrict__ out) {
    cudaGridDependencySynchronize();
    const __half* __restrict__ rbuf =
        ((NUM_ITER - 1) & 1) ? g_msgB : g_msgA;
    __shared__ float tile[32][129];
    __shared__ float red[BP4 / 32];

    const int v0 = blockIdx.x * 32;
    const int tx = threadIdx.x & 31;
    const int ty = threadIdx.x >> 5;   // warp 0..9
    float sp = 0.0f;

    for (int bc = 0; bc < BP / 128; bc++) {
#pragma unroll
        for (int r = ty; r < 32; r += 10) {
            int v = v0 + r;
            int b = bc * 128 + tx * 4;
            size_t base = (size_t)v * BP + b;
            h4 h0 = *(const h4*)(rbuf + base);
            h4 h1 = *(const h4*)(rbuf + (size_t)N_VN * BP + base);
            h4 h2 = *(const h4*)(rbuf + (size_t)2 * N_VN * BP + base);
            const float4 Lv = *(const float4*)(g_L + base);
            float2 s0 = __half22float2(__hadd2(__hadd2(h0.a, h1.a), h2.a));
            float2 s1 = __half22float2(__hadd2(__hadd2(h0.b, h1.b), h2.b));
            float xv[4];
            xv[0] = Lv.x + s0.x;  xv[1] = Lv.y + s0.y;
            xv[2] = Lv.z + s1.x;  xv[3] = Lv.w + s1.y;
#pragma unroll
            for (int k = 0; k < 4; k++) {
                tile[r][tx * 4 + k] = xv[k];
                if (b + k < BATCH) {
                    float ch = -xv[k];
                    sp += fmaxf(ch, 0.0f) + __logf(1.0f + __expf(-fabsf(ch)));
                }
            }
        }
        __syncthreads();
        for (int m = ty; m < 128; m += 10) {
            int b = bc * 128 + m;
            if (b < BATCH)
                out[OUT_CHAT + (size_t)b * N_VN + v0 + tx] = -tile[tx][m];
        }
        __syncthreads();
    }

    for (int o = 16; o > 0; o >>= 1)
        sp += __shfl_down_sync(0xffffffffu, sp, o);
    if (tx == 0) red[ty] = sp;
    __syncthreads();
    if (threadIdx.x == 0) {
        float s = 0.0f;
#pragma unroll
        for (int w = 0; w < BP4 / 32; w++) s += red[w];
        atomicAdd(&g_loss, (double)s);
    }
}

// ---------------------------------------------------------------------------
__global__ void loss_kernel(float* __restrict__ out) {
    cudaGridDependencySynchronize();
    if (threadIdx.x == 0 && blockIdx.x == 0) {
        double denom = (double)NUM_ITER * (double)BATCH * (double)N_VN;
        out[OUT_LOSS] = (float)(g_loss / denom);
    }
}

// ---------------------------------------------------------------------------
// PDL launch helper: overlap next-kernel dispatch with current-kernel tail.
template <typename... Args>
static void launch_pdl(void (*kern)(Args...), dim3 grid, dim3 block,
                       Args... args) {
    cudaLaunchConfig_t cfg = {};
    cfg.gridDim = grid;
    cfg.blockDim = block;
    cudaLaunchAttribute attr[1];
    attr[0].id = cudaLaunchAttributeProgrammaticStreamSerialization;
    attr[0].val.programmaticStreamSerializationAllowed = 1;
    cfg.attrs = attr;
    cfg.numAttrs = 1;
    cudaLaunchKernelEx(&cfg, kern, args...);
}

extern "C" void kernel_launch(void* const* d_in, const int* in_sizes, int n_in,
                              void* d_out, int out_size) {
    const float* noise   = (const float*)d_in[0];
    const float* weights = (const float*)d_in[1];
    // d_in[2] = vn_idx (tile(arange(N_VN), DV) by construction; implicit)
    const int*   cn_idx  = (const int*)d_in[3];
    const int*   ebno    = (const int*)d_in[4];
    float* out = (float*)d_out;

    // c output = zeros
    cudaMemsetAsync(out, 0, (size_t)BATCH * N_VN * sizeof(float));

    dim3 tb(32, 32);
    dim3 tg(N_VN / 32, (BATCH + 31) / 32);   // 250 x 40
    launch_pdl(init_kernel, tg, tb, noise, ebno, out);
    launch_pdl(build_csr_kernel, dim3((NEDGE + 255) / 256), dim3(256), cn_idx);

    for (int it = 0; it < NUM_ITER; it++)
        launch_pdl(fused_cn_kernel, dim3(N_CN), dim3(BP4), weights, it);

    launch_pdl(vn_last_kernel, dim3(N_VN / 32), dim3(BP4), out);
    launch_pdl(loss_kernel, dim3(1), dim3(32), out);
}

// round 9
// speedup vs baseline: 1.3059x; 1.0522x over previous
#include <cuda_runtime.h>
#include <cuda_fp16.h>
#include <math.h>

// Problem constants (fixed shapes per reference)
#define N_VN   8000
#define N_CN   4000
#define DV     3
#define DC     6
#define BATCH  1250
#define BP     1280          // padded batch stride (128B aligned rows)
#define BP4    (BP/4)        // 320 4-wide lanes
#define SLICE  640           // batch columns per slice (2 slices)
#define SL4    (SLICE/4)     // 160 threads per cn block
#define NEDGE  (DV * N_VN)   // 24000
#define NUM_ITER 5

// Output layout: [c (B*n zeros)][c_hat (B*n)][llr (B*n)][loss (1)]
#define OUT_CHAT  ((size_t)BATCH * N_VN)
#define OUT_LLR   ((size_t)2 * BATCH * N_VN)
#define OUT_LOSS  ((size_t)3 * BATCH * N_VN)

struct alignas(8) h4 { __half2 a, b; };

// Scratch (device globals; no allocation allowed)
__device__ float  g_L[(size_t)N_VN * BP];          // 40 MB  L[v][b]
__device__ __half g_msgA[(size_t)NEDGE * BP];      // 60 MB  message ping buffer
__device__ __half g_msgB[(size_t)NEDGE * BP];      // 60 MB  message pong buffer
__device__ int    g_cn_edges[NEDGE];               // CSR: 6 edges per CN
__device__ int    g_cn_cnt[N_CN];
__device__ double g_loss;

__device__ __forceinline__ float tanh_approx(float x) {
    float r;
    asm("tanh.approx.f32 %0, %1;" : "=f"(r) : "f"(x));
    return r;
}

// ---------------------------------------------------------------------------
// Init: llr output (coalesced), transpose to L[v][b]. Zeroes CSR counters +
// loss. Pad batch lanes [1250,1280) get zeros.
__global__ void init_kernel(const float* __restrict__ noise,
                            const int* __restrict__ ebno_p,
                            float* __restrict__ out) {
    cudaGridDependencySynchronize();
    __shared__ float tile[32][33];

    int gid = (blockIdx.y * gridDim.x + blockIdx.x) * 1024
            + threadIdx.y * 32 + threadIdx.x;
    if (gid < N_CN) g_cn_cnt[gid] = 0;
    if (gid == N_CN) g_loss = 0.0;

    // sigma2 = 4/no, no = 1/(10^(ebno/10)*0.5)  =>  sigma2 = 2*10^(ebno/10)
    int iv = ebno_p[0];
    float eb = (iv >= -100 && iv <= 100) ? (float)iv : __int_as_float(iv);
    float sigma2 = 2.0f * exp10f(eb * 0.1f);
    float half_s2 = 0.5f * sigma2;
    float sq = sqrtf(sigma2);

    int v = blockIdx.x * 32 + threadIdx.x;   // 250 tiles * 32 == 8000 exact
    int b = blockIdx.y * 32 + threadIdx.y;

    float Lval = 0.0f;
    if (b < BATCH) {
        float llr = fmaf(sq, noise[(size_t)b * N_VN + v], -half_s2);
        out[OUT_LLR + (size_t)b * N_VN + v] = llr;   // coalesced
        Lval = -llr;                                 // L = -llr.T
    }
    tile[threadIdx.y][threadIdx.x] = Lval;
    __syncthreads();

    int v2 = blockIdx.x * 32 + threadIdx.y;
    int b2 = blockIdx.y * 32 + threadIdx.x;          // always < BP
    g_L[(size_t)v2 * BP + b2] = tile[threadIdx.x][threadIdx.y];
    cudaTriggerProgrammaticLaunchCompletion();
}

// ---------------------------------------------------------------------------
__global__ void build_csr_kernel(const int* __restrict__ cn_idx) {
    cudaGridDependencySynchronize();   // counters zeroed by init
    int e = blockIdx.x * blockDim.x + threadIdx.x;
    if (e < NEDGE) {
        int c = cn_idx[e];
        int s = atomicAdd(&g_cn_cnt[c], 1);
        g_cn_edges[c * DC + s] = e;    // order irrelevant (exclusive product)
    }
    cudaTriggerProgrammaticLaunchCompletion();
}

// ---------------------------------------------------------------------------
// Fused CN update (VN recompute folded in), one batch SLICE per launch.
// 160 threads cover 640 batch cols (4/thread). All 5 iterations of a slice
// run back-to-back so the slice working set (L 20MB + msg 2x30MB = 80MB)
// stays L2-resident across iterations.
// DOUBLE-BUFFERED across iterations: read rbuf, write wbuf.
__global__ __launch_bounds__(SL4, 8) void fused_cn_kernel(
        const float* __restrict__ weights, int it, int bbase) {
    cudaGridDependencySynchronize();
    const __half* __restrict__ rbuf = (it & 1) ? g_msgA : g_msgB;  // prev iter
    __half* __restrict__       wbuf = (it & 1) ? g_msgB : g_msgA;  // this iter

    __shared__ int   se[DC];
    __shared__ int   sv[DC];
    __shared__ int   sl[DC];
    __shared__ float sw2[DC];
    __shared__ float red[SL4 / 32];

    int c = blockIdx.x;
    if (threadIdx.x < DC) {
        int e = g_cn_edges[c * DC + threadIdx.x];
        se[threadIdx.x] = e;
        sv[threadIdx.x] = e % N_VN;    // vn_idx = tile(arange(N_VN), DV)
        sl[threadIdx.x] = e / N_VN;    // layer 0..2
        sw2[threadIdx.x] = 0.5f * weights[e];
    }
    __syncthreads();

    const bool first = (it == 0);
    const int  b0   = bbase + threadIdx.x * 4;
    const size_t boff = (size_t)b0;
    float loss_acc = 0.0f;

    float4 t[DC];
#pragma unroll
    for (int j = 0; j < DC; j++) {
        const int v = sv[j];
        float4 x = *(const float4*)(g_L + (size_t)v * BP + boff);
        float4 marg = make_float4(0.f, 0.f, 0.f, 0.f);
        if (!first) {
            h4 m0 = *(const h4*)(rbuf + (size_t)v * BP + boff);
            h4 m1 = *(const h4*)(rbuf + (size_t)(v + N_VN) * BP + boff);
            h4 m2 = *(const h4*)(rbuf + (size_t)(v + 2 * N_VN) * BP + boff);
            // x = L + half2-sum (bit-identical to the old vn_kernel path)
            float2 s0 = __half22float2(__hadd2(__hadd2(m0.a, m1.a), m2.a));
            float2 s1 = __half22float2(__hadd2(__hadd2(m0.b, m1.b), m2.b));
            x.x += s0.x;  x.y += s0.y;  x.z += s1.x;  x.w += s1.y;
            // select this edge's own message (by layer)
            int l = sl[j];
            __half2 ma = (l == 0) ? m0.a : (l == 1) ? m1.a : m2.a;
            __half2 mb = (l == 0) ? m0.b : (l == 1) ? m1.b : m2.b;
            float2 f0 = __half22float2(ma);
            float2 f1 = __half22float2(mb);
            marg = make_float4(f0.x, f0.y, f1.x, f1.y);
            // loss of iteration it-1, owned by the VN's unique layer-0 edge
            if (l == 0) {
#pragma unroll
                for (int k = 0; k < 4; k++) {
                    if (b0 + k < BATCH) {
                        float ch = -(&x.x)[k];
                        loss_acc += fmaxf(ch, 0.0f)
                                  + __logf(1.0f + __expf(-fabsf(ch)));
                    }
                }
            }
        }
        float w2 = sw2[j];
#pragma unroll
        for (int k = 0; k < 4; k++)
            (&t[j].x)[k] = tanh_approx(((&x.x)[k] - (&marg.x)[k]) * w2);
    }

    // split-half exclusive signed product
    float A[4], B[4];
#pragma unroll
    for (int k = 0; k < 4; k++) {
        A[k] = (&t[0].x)[k] * (&t[1].x)[k] * (&t[2].x)[k];
        B[k] = (&t[3].x)[k] * (&t[4].x)[k] * (&t[5].x)[k];
    }
#pragma unroll
    for (int j = 0; j < DC; j++) {
        int ja = (j < 3) ? ((j + 1) % 3) : (3 + (j - 2) % 3);
        int jb = (j < 3) ? ((j + 2) % 3) : (3 + (j - 1) % 3);
        float4 msg;
#pragma unroll
        for (int k = 0; k < 4; k++) {
            float other = (j < 3) ? B[k] : A[k];
            float p = (&t[ja].x)[k] * (&t[jb].x)[k] * other;
            p = fminf(fmaxf(p, -1.0f + 1e-7f), 1.0f - 1e-7f);
            (&msg.x)[k] = __logf(__fdividef(1.0f + p, 1.0f - p));  // 2*atanh
        }
        h4 h;
        h.a = __floats2half2_rn(msg.x, msg.y);
        h.b = __floats2half2_rn(msg.z, msg.w);
        *(h4*)(wbuf + (size_t)se[j] * BP + boff) = h;
    }
    cudaTriggerProgrammaticLaunchCompletion();

    if (!first) {
        for (int o = 16; o > 0; o >>= 1)
            loss_acc += __shfl_down_sync(0xffffffffu, loss_acc, o);
        if ((threadIdx.x & 31) == 0) red[threadIdx.x >> 5] = loss_acc;
        __syncthreads();
        if (threadIdx.x == 0) {
            float s = 0.0f;
#pragma unroll
            for (int w = 0; w < SL4 / 32; w++) s += red[w];
            atomicAdd(&g_loss, (double)s);
        }
    }
}

// ---------------------------------------------------------------------------
// Final VN pass fused with c_hat transpose: x_4 per 32-VN tile, its loss,
// and c_hat[b][v] = -x written coalesced via shared transpose.
// Reads the buffer written by iteration NUM_ITER-1 (both slices land there).
__global__ __launch_bounds__(BP4) void vn_last_kernel(float* __restrict__ out) {
    cudaGridDependencySynchronize();
    const __half* __restrict__ rbuf =
        ((NUM_ITER - 1) & 1) ? g_msgB : g_msgA;
    __shared__ float tile[32][129];
    __shared__ float red[BP4 / 32];

    const int v0 = blockIdx.x * 32;
    const int tx = threadIdx.x & 31;
    const int ty = threadIdx.x >> 5;   // warp 0..9
    float sp = 0.0f;

    for (int bc = 0; bc < BP / 128; bc++) {
#pragma unroll
        for (int r = ty; r < 32; r += 10) {
            int v = v0 + r;
            int b = bc * 128 + tx * 4;
            size_t base = (size_t)v * BP + b;
            h4 h0 = *(const h4*)(rbuf + base);
            h4 h1 = *(const h4*)(rbuf + (size_t)N_VN * BP + base);
            h4 h2 = *(const h4*)(rbuf + (size_t)2 * N_VN * BP + base);
            const float4 Lv = *(const float4*)(g_L + base);
            float2 s0 = __half22float2(__hadd2(__hadd2(h0.a, h1.a), h2.a));
            float2 s1 = __half22float2(__hadd2(__hadd2(h0.b, h1.b), h2.b));
            float xv[4];
            xv[0] = Lv.x + s0.x;  xv[1] = Lv.y + s0.y;
            xv[2] = Lv.z + s1.x;  xv[3] = Lv.w + s1.y;
#pragma unroll
            for (int k = 0; k < 4; k++) {
                tile[r][tx * 4 + k] = xv[k];
                if (b + k < BATCH) {
                    float ch = -xv[k];
                    sp += fmaxf(ch, 0.0f) + __logf(1.0f + __expf(-fabsf(ch)));
                }
            }
        }
        __syncthreads();
        for (int m = ty; m < 128; m += 10) {
            int b = bc * 128 + m;
            if (b < BATCH)
                out[OUT_CHAT + (size_t)b * N_VN + v0 + tx] = -tile[tx][m];
        }
        __syncthreads();
    }

    for (int o = 16; o > 0; o >>= 1)
        sp += __shfl_down_sync(0xffffffffu, sp, o);
    if (tx == 0) red[ty] = sp;
    __syncthreads();
    if (threadIdx.x == 0) {
        float s = 0.0f;
#pragma unroll
        for (int w = 0; w < BP4 / 32; w++) s += red[w];
        atomicAdd(&g_loss, (double)s);
    }
}

// ---------------------------------------------------------------------------
__global__ void loss_kernel(float* __restrict__ out) {
    cudaGridDependencySynchronize();
    if (threadIdx.x == 0 && blockIdx.x == 0) {
        double denom = (double)NUM_ITER * (double)BATCH * (double)N_VN;
        out[OUT_LOSS] = (float)(g_loss / denom);
    }
}

// ---------------------------------------------------------------------------
// PDL launch helper: overlap next-kernel dispatch with current-kernel tail.
template <typename... Args>
static void launch_pdl(void (*kern)(Args...), dim3 grid, dim3 block,
                       Args... args) {
    cudaLaunchConfig_t cfg = {};
    cfg.gridDim = grid;
    cfg.blockDim = block;
    cudaLaunchAttribute attr[1];
    attr[0].id = cudaLaunchAttributeProgrammaticStreamSerialization;
    attr[0].val.programmaticStreamSerializationAllowed = 1;
    cfg.attrs = attr;
    cfg.numAttrs = 1;
    cudaLaunchKernelEx(&cfg, kern, args...);
}

extern "C" void kernel_launch(void* const* d_in, const int* in_sizes, int n_in,
                              void* d_out, int out_size) {
    const float* noise   = (const float*)d_in[0];
    const float* weights = (const float*)d_in[1];
    // d_in[2] = vn_idx (tile(arange(N_VN), DV) by construction; implicit)
    const int*   cn_idx  = (const int*)d_in[3];
    const int*   ebno    = (const int*)d_in[4];
    float* out = (float*)d_out;

    // c output = zeros
    cudaMemsetAsync(out, 0, (size_t)BATCH * N_VN * sizeof(float));

    dim3 tb(32, 32);
    dim3 tg(N_VN / 32, (BATCH + 31) / 32);   // 250 x 40
    launch_pdl(init_kernel, tg, tb, noise, ebno, out);
    launch_pdl(build_csr_kernel, dim3((NEDGE + 255) / 256), dim3(256), cn_idx);

    // Batch-sliced iteration loop: all 5 iterations of a slice back-to-back
    // so its 80 MB working set stays L2-resident.
    for (int s = 0; s < BP / SLICE; s++)
        for (int it = 0; it < NUM_ITER; it++)
            launch_pdl(fused_cn_kernel, dim3(N_CN), dim3(SL4),
                       weights, it, s * SLICE);

    launch_pdl(vn_last_kernel, dim3(N_VN / 32), dim3(BP4), out);
    launch_pdl(loss_kernel, dim3(1), dim3(32), out);
}